// round 6
// baseline (speedup 1.0000x reference)
#include <cuda_runtime.h>
#include <math.h>

#define W_    640
#define H_    480
#define HW_   (W_ * H_)
#define CIN   14
#define COUT  15
#define TPB   256
#define BLKS_PER_VIEW (HW_ / TPB)   // 1200

struct ViewConst {
    float M[9];   // inv(intrinsics)
    float R[9];   // extrinsics rotation
    float t[3];   // extrinsics translation
    float mult;   // sum(inv(intr[:2,:2]))
};

__device__ __forceinline__ float sigmoidf_(float x) {
    return __fdividef(1.0f, 1.0f + __expf(-x));
}
__device__ __forceinline__ float softplusf_(float x) {
    float l = __logf(1.0f + __expf(-fabsf(x)));
    return x > 0.0f ? x + l : l;
}

__global__ __launch_bounds__(TPB, 8) void splat_kernel(const float* __restrict__ raw,
                                                       const float* __restrict__ ext,
                                                       const float* __restrict__ intr,
                                                       float* __restrict__ out) {
    __shared__ float s[TPB * COUT];
    __shared__ ViewConst svc;

    int vi  = blockIdx.x / BLKS_PER_VIEW;
    int pix = (blockIdx.x - vi * BLKS_PER_VIEW) * TPB + threadIdx.x;
    int y   = pix / W_;
    int x   = pix - y * W_;

    const float* base = raw + vi * (CIN * HW_) + pix;

    // ---- batch A: "light" channels -> activations, parked in smem early ----
    float a0 = __ldcs(base + 0 * HW_);
    float a1 = __ldcs(base + 1 * HW_);
    float a2 = __ldcs(base + 2 * HW_);
    float a4 = __ldcs(base + 4 * HW_);
    float a5 = __ldcs(base + 5 * HW_);
    float a6 = __ldcs(base + 6 * HW_);
    float a7 = __ldcs(base + 7 * HW_);
    // ---- batch B: "heavy" channels, consumed by geometry path ----
    float h3  = __ldcs(base + 3 * HW_);
    float h8  = __ldcs(base + 8 * HW_);
    float h9  = __ldcs(base + 9 * HW_);
    float h10 = __ldcs(base + 10 * HW_);
    float h11 = __ldcs(base + 11 * HW_);
    float h12 = __ldcs(base + 12 * HW_);
    float h13 = __ldcs(base + 13 * HW_);

    // per-view constants: one thread per block
    if (threadIdx.x == 0) {
        const float* K = intr + vi * 9;
        float a = K[0], b = K[1], c = K[2];
        float d = K[3], e = K[4], f = K[5];
        float g = K[6], h = K[7], k = K[8];
        float A = e * k - f * h;
        float B = f * g - d * k;
        float C = d * h - e * g;
        float inv = __fdividef(1.0f, a * A + b * B + c * C);
        svc.M[0] = A * inv;  svc.M[1] = (c * h - b * k) * inv;  svc.M[2] = (b * f - c * e) * inv;
        svc.M[3] = B * inv;  svc.M[4] = (a * k - c * g) * inv;  svc.M[5] = (c * d - a * f) * inv;
        svc.M[6] = C * inv;  svc.M[7] = (b * g - a * h) * inv;  svc.M[8] = (a * e - b * d) * inv;
        const float* E = ext + vi * 16;
#pragma unroll
        for (int r = 0; r < 3; r++) {
            svc.R[r * 3 + 0] = E[r * 4 + 0];
            svc.R[r * 3 + 1] = E[r * 4 + 1];
            svc.R[r * 3 + 2] = E[r * 4 + 2];
            svc.t[r]         = E[r * 4 + 3];
        }
        svc.mult = __fdividef(a + e - b - d, a * e - b * d);
    }
    __syncthreads();

    // light path first: activations into smem, freeing 7 registers for the
    // heavy quaternion path below.
    float mult = svc.mult;
    float* sp = s + threadIdx.x * COUT;   // stride 15 (odd) -> conflict-free
    sp[3]  = 1.0f;
    sp[4]  = softplusf_(a0);
    sp[5]  = softplusf_(a1);
    sp[6]  = softplusf_(a2);
    sp[7]  = sigmoidf_(a4);
    sp[8]  = softplusf_(a5) * mult;
    sp[9]  = softplusf_(a6) * mult;
    sp[10] = softplusf_(a7) * mult;

    float R0 = svc.R[0], R1 = svc.R[1], R2 = svc.R[2];
    float R3 = svc.R[3], R4 = svc.R[4], R5 = svc.R[5];
    float R6 = svc.R[6], R7 = svc.R[7], R8 = svc.R[8];

    // pixel coords + sigmoid offset, unproject through inv(K)
    float cx = (float)x + sigmoidf_(h12) - 0.5f;
    float cy = (float)y + sigmoidf_(h13) - 0.5f;
    float dx = svc.M[0] * cx + svc.M[1] * cy + svc.M[2];
    float dy = svc.M[3] * cx + svc.M[4] * cy + svc.M[5];
    float dz = svc.M[6] * cx + svc.M[7] * cy + svc.M[8];
    float dn = rsqrtf(dx * dx + dy * dy + dz * dz);
    dx *= dn; dy *= dn; dz *= dn;

    // rotate to world (homogeneous w=0 -> rotation only)
    float wdx = R0 * dx + R1 * dy + R2 * dz;
    float wdy = R3 * dx + R4 * dy + R5 * dz;
    float wdz = R6 * dx + R7 * dy + R8 * dz;

    float disp  = sigmoidf_(h3);
    float depth = __fdividef(1.0f, disp * (1.0f / 0.05f - 1.0f / 20.0f) + 1.0f / 20.0f);

    sp[0] = svc.t[0] + wdx * depth;
    sp[1] = svc.t[1] + wdy * depth;
    sp[2] = svc.t[2] + wdz * depth;

    // quaternion (x,y,z,w) -> rotation matrix
    float qx = h8, qy = h9, qz = h10, qw = h11;
    float qn = rsqrtf(qx * qx + qy * qy + qz * qz + qw * qw);
    qx *= qn; qy *= qn; qz *= qn; qw *= qn;

    float c00 = 1.0f - 2.0f * (qy * qy + qz * qz);
    float c01 = 2.0f * (qx * qy - qz * qw);
    float c02 = 2.0f * (qx * qz + qy * qw);
    float c10 = 2.0f * (qx * qy + qz * qw);
    float c11 = 1.0f - 2.0f * (qx * qx + qz * qz);
    float c12 = 2.0f * (qy * qz - qx * qw);
    float c20 = 2.0f * (qx * qz - qy * qw);
    float c21 = 2.0f * (qy * qz + qx * qw);
    float c22 = 1.0f - 2.0f * (qx * qx + qy * qy);

    // m = R_ext * cam_m
    float m00 = R0 * c00 + R1 * c10 + R2 * c20;
    float m01 = R0 * c01 + R1 * c11 + R2 * c21;
    float m02 = R0 * c02 + R1 * c12 + R2 * c22;
    float m10 = R3 * c00 + R4 * c10 + R5 * c20;
    float m11 = R3 * c01 + R4 * c11 + R5 * c21;
    float m12 = R3 * c02 + R4 * c12 + R5 * c22;
    float m20 = R6 * c00 + R7 * c10 + R8 * c20;
    float m21 = R6 * c01 + R7 * c11 + R8 * c21;
    float m22 = R6 * c02 + R7 * c12 + R8 * c22;

    float tr = m00 + m11 + m22;
    // argmax([m00,m11,m22,tr]) with first-occurrence tie rule
    int choice = 0; float best = m00;
    if (m11 > best) { best = m11; choice = 1; }
    if (m22 > best) { best = m22; choice = 2; }
    if (tr  > best) {             choice = 3; }

    float q0, q1, q2, q3;
    if (choice == 0)      { q0 = m21 - m12; q1 = 1.0f + m00 - m11 - m22; q2 = m01 + m10; q3 = m02 + m20; }
    else if (choice == 1) { q0 = m02 - m20; q1 = m01 + m10; q2 = 1.0f + m11 - m00 - m22; q3 = m12 + m21; }
    else if (choice == 2) { q0 = m10 - m01; q1 = m02 + m20; q2 = m12 + m21; q3 = 1.0f + m22 - m00 - m11; }
    else                  { q0 = 1.0f + tr; q1 = m21 - m12; q2 = m02 - m20; q3 = m10 - m01; }
    float qrn = rsqrtf(q0 * q0 + q1 * q1 + q2 * q2 + q3 * q3);
    sp[11] = q0 * qrn; sp[12] = q1 * qrn; sp[13] = q2 * qrn; sp[14] = q3 * qrn;
    __syncthreads();

    // coalesced 16B-vector streaming writeback: 256*15*4 = 15360 B, 16B aligned
    float*        ob = out + (size_t)blockIdx.x * (TPB * COUT);
    const float4* s4 = reinterpret_cast<const float4*>(s);
#pragma unroll
    for (int i = threadIdx.x; i < TPB * COUT / 4; i += TPB) {
        float4 val = s4[i];
        __stcs(reinterpret_cast<float4*>(ob) + i, val);
    }
}

extern "C" void kernel_launch(void* const* d_in, const int* in_sizes, int n_in,
                              void* d_out, int out_size) {
    const float* raw  = (const float*)d_in[0];
    const float* ext  = (const float*)d_in[1];
    const float* intr = (const float*)d_in[2];
    int v = in_sizes[1] / 16;                 // extrinsics (b*v,4,4) -> v = 8
    splat_kernel<<<v * BLKS_PER_VIEW, TPB>>>(raw, ext, intr, (float*)d_out);
}

// round 7
// speedup vs baseline: 1.0164x; 1.0164x over previous
#include <cuda_runtime.h>
#include <math.h>

#define W_    640
#define H_    480
#define HW_   (W_ * H_)
#define CIN   14
#define COUT  15
#define TPB   256
#define BLKS_PER_VIEW (HW_ / TPB)   // 1200

struct ViewConst {
    float M[9];   // inv(intrinsics)
    float R[9];   // extrinsics rotation
    float t[3];   // extrinsics translation
    float mult;   // sum(inv(intr[:2,:2]))
};

__device__ __forceinline__ float sigmoidf_(float x) {
    return __fdividef(1.0f, 1.0f + __expf(-x));
}
__device__ __forceinline__ float softplusf_(float x) {
    float l = __logf(1.0f + __expf(-fabsf(x)));
    return x > 0.0f ? x + l : l;
}

__global__ __launch_bounds__(TPB) void splat_kernel(const float* __restrict__ raw,
                                                    const float* __restrict__ ext,
                                                    const float* __restrict__ intr,
                                                    float* __restrict__ out) {
    __shared__ float s[TPB * COUT];
    __shared__ ViewConst svc;

    int vi  = blockIdx.x / BLKS_PER_VIEW;
    int pix = (blockIdx.x - vi * BLKS_PER_VIEW) * TPB + threadIdx.x;
    int y   = pix / W_;
    int x   = pix - y * W_;

    // channel loads first: independent of the barrier, latency overlaps prep
    const float* base = raw + vi * (CIN * HW_) + pix;
    float ch[CIN];
#pragma unroll
    for (int c = 0; c < CIN; c++) ch[c] = __ldg(base + c * HW_);

    // per-view constants: one thread per block (L1-cached loads, ~60 flops)
    if (threadIdx.x == 0) {
        const float* K = intr + vi * 9;
        float a = K[0], b = K[1], c = K[2];
        float d = K[3], e = K[4], f = K[5];
        float g = K[6], h = K[7], k = K[8];
        float A = e * k - f * h;
        float B = f * g - d * k;
        float C = d * h - e * g;
        float inv = __fdividef(1.0f, a * A + b * B + c * C);
        svc.M[0] = A * inv;  svc.M[1] = (c * h - b * k) * inv;  svc.M[2] = (b * f - c * e) * inv;
        svc.M[3] = B * inv;  svc.M[4] = (a * k - c * g) * inv;  svc.M[5] = (c * d - a * f) * inv;
        svc.M[6] = C * inv;  svc.M[7] = (b * g - a * h) * inv;  svc.M[8] = (a * e - b * d) * inv;
        const float* E = ext + vi * 16;
#pragma unroll
        for (int r = 0; r < 3; r++) {
            svc.R[r * 3 + 0] = E[r * 4 + 0];
            svc.R[r * 3 + 1] = E[r * 4 + 1];
            svc.R[r * 3 + 2] = E[r * 4 + 2];
            svc.t[r]         = E[r * 4 + 3];
        }
        svc.mult = __fdividef(a + e - b - d, a * e - b * d);
    }
    __syncthreads();   // only block-wide barrier; hidden under the 14 LDGs

    float R0 = svc.R[0], R1 = svc.R[1], R2 = svc.R[2];
    float R3 = svc.R[3], R4 = svc.R[4], R5 = svc.R[5];
    float R6 = svc.R[6], R7 = svc.R[7], R8 = svc.R[8];

    // pixel coords + sigmoid offset, unproject through inv(K)
    float cx = (float)x + sigmoidf_(ch[12]) - 0.5f;
    float cy = (float)y + sigmoidf_(ch[13]) - 0.5f;
    float dx = svc.M[0] * cx + svc.M[1] * cy + svc.M[2];
    float dy = svc.M[3] * cx + svc.M[4] * cy + svc.M[5];
    float dz = svc.M[6] * cx + svc.M[7] * cy + svc.M[8];
    float dn = rsqrtf(dx * dx + dy * dy + dz * dz);
    dx *= dn; dy *= dn; dz *= dn;

    // rotate to world (homogeneous w=0 -> rotation only)
    float wdx = R0 * dx + R1 * dy + R2 * dz;
    float wdy = R3 * dx + R4 * dy + R5 * dz;
    float wdz = R6 * dx + R7 * dy + R8 * dz;

    float disp  = sigmoidf_(ch[3]);
    float depth = __fdividef(1.0f, disp * (1.0f / 0.05f - 1.0f / 20.0f) + 1.0f / 20.0f);

    float mx = svc.t[0] + wdx * depth;
    float my = svc.t[1] + wdy * depth;
    float mz = svc.t[2] + wdz * depth;

    // quaternion (x,y,z,w) -> rotation matrix
    float qx = ch[8], qy = ch[9], qz = ch[10], qw = ch[11];
    float qn = rsqrtf(qx * qx + qy * qy + qz * qz + qw * qw);
    qx *= qn; qy *= qn; qz *= qn; qw *= qn;

    float c00 = 1.0f - 2.0f * (qy * qy + qz * qz);
    float c01 = 2.0f * (qx * qy - qz * qw);
    float c02 = 2.0f * (qx * qz + qy * qw);
    float c10 = 2.0f * (qx * qy + qz * qw);
    float c11 = 1.0f - 2.0f * (qx * qx + qz * qz);
    float c12 = 2.0f * (qy * qz - qx * qw);
    float c20 = 2.0f * (qx * qz - qy * qw);
    float c21 = 2.0f * (qy * qz + qx * qw);
    float c22 = 1.0f - 2.0f * (qx * qx + qy * qy);

    // m = R_ext * cam_m
    float m00 = R0 * c00 + R1 * c10 + R2 * c20;
    float m01 = R0 * c01 + R1 * c11 + R2 * c21;
    float m02 = R0 * c02 + R1 * c12 + R2 * c22;
    float m10 = R3 * c00 + R4 * c10 + R5 * c20;
    float m11 = R3 * c01 + R4 * c11 + R5 * c21;
    float m12 = R3 * c02 + R4 * c12 + R5 * c22;
    float m20 = R6 * c00 + R7 * c10 + R8 * c20;
    float m21 = R6 * c01 + R7 * c11 + R8 * c21;
    float m22 = R6 * c02 + R7 * c12 + R8 * c22;

    float tr = m00 + m11 + m22;
    // argmax([m00,m11,m22,tr]) with first-occurrence tie rule
    int choice = 0; float best = m00;
    if (m11 > best) { best = m11; choice = 1; }
    if (m22 > best) { best = m22; choice = 2; }
    if (tr  > best) {             choice = 3; }

    float q0, q1, q2, q3;
    if (choice == 0)      { q0 = m21 - m12; q1 = 1.0f + m00 - m11 - m22; q2 = m01 + m10; q3 = m02 + m20; }
    else if (choice == 1) { q0 = m02 - m20; q1 = m01 + m10; q2 = 1.0f + m11 - m00 - m22; q3 = m12 + m21; }
    else if (choice == 2) { q0 = m10 - m01; q1 = m02 + m20; q2 = m12 + m21; q3 = 1.0f + m22 - m00 - m11; }
    else                  { q0 = 1.0f + tr; q1 = m21 - m12; q2 = m02 - m20; q3 = m10 - m01; }
    float qrn = rsqrtf(q0 * q0 + q1 * q1 + q2 * q2 + q3 * q3);
    q0 *= qrn; q1 *= qrn; q2 *= qrn; q3 *= qrn;

    // stage 15 channels/pixel in this warp's private smem slice
    float mult = svc.mult;
    float* sp = s + threadIdx.x * COUT;   // stride 15 (odd) -> conflict-free
    sp[0]  = mx; sp[1] = my; sp[2] = mz; sp[3] = 1.0f;
    sp[4]  = softplusf_(ch[0]);
    sp[5]  = softplusf_(ch[1]);
    sp[6]  = softplusf_(ch[2]);
    sp[7]  = sigmoidf_(ch[4]);
    sp[8]  = softplusf_(ch[5]) * mult;
    sp[9]  = softplusf_(ch[6]) * mult;
    sp[10] = softplusf_(ch[7]) * mult;
    sp[11] = q0; sp[12] = q1; sp[13] = q2; sp[14] = q3;

    // warp-autonomous writeback: no block barrier, warps free-run.
    __syncwarp();
    int warp = threadIdx.x >> 5;
    int lane = threadIdx.x & 31;
    const float4* s4 = reinterpret_cast<const float4*>(s + warp * (32 * COUT));
    float4*       o4 = reinterpret_cast<float4*>(
        out + ((size_t)blockIdx.x * TPB + warp * 32) * COUT);
#pragma unroll
    for (int i = lane; i < 32 * COUT / 4; i += 32)   // 120 float4 per warp
        o4[i] = s4[i];
}

extern "C" void kernel_launch(void* const* d_in, const int* in_sizes, int n_in,
                              void* d_out, int out_size) {
    const float* raw  = (const float*)d_in[0];
    const float* ext  = (const float*)d_in[1];
    const float* intr = (const float*)d_in[2];
    int v = in_sizes[1] / 16;                 // extrinsics (b*v,4,4) -> v = 8
    splat_kernel<<<v * BLKS_PER_VIEW, TPB>>>(raw, ext, intr, (float*)d_out);
}